// round 5
// baseline (speedup 1.0000x reference)
#include <cuda_runtime.h>

// Problem constants (fixed by the reference):
//   input : (32, 1, 1024, 1024) float32
//   x_A, y_A, x_B, y_B, ordinal : (32, 100000) int32
//   output: scalar float32 = mean loss over 3.2M points
#define BB    32
#define HH    1024
#define WW    1024
#define NPTS  100000
#define TOTAL (BB * NPTS)        // 3,200,000
#define PPT   8                  // points per thread (NPTS % 8 == 0)
#define NTHREADS (TOTAL / PPT)   // 400,000
#define TPB   256
#define NBLOCKS ((NTHREADS + TPB - 1) / TPB)  // 1563 (last block partial)

__device__ double       g_acc   = 0.0;
__device__ unsigned int g_count = 0;

__global__ __launch_bounds__(TPB, 8) void loss_kernel(
    const float* __restrict__ depth,
    const int*   __restrict__ xA,
    const int*   __restrict__ yA,
    const int*   __restrict__ xB,
    const int*   __restrict__ yB,
    const int*   __restrict__ ordv,
    float*       __restrict__ out)
{
    const int t = blockIdx.x * TPB + threadIdx.x;   // 0 .. 400127

    float l = 0.0f;
    if (t < NTHREADS) {
        // NPTS % 8 == 0 -> all 8 points of this thread share one batch
        const int b = t / (NPTS / PPT);             // t / 12500
        const float* __restrict__ img = depth + (size_t)b * (HH * WW);

        const int4* xA4 = (const int4*)xA;
        const int4* yA4 = (const int4*)yA;
        const int4* xB4 = (const int4*)xB;
        const int4* yB4 = (const int4*)yB;
        const int4* ov4 = (const int4*)ordv;

        // A-side: load coords, fold into flat offsets immediately (register economy)
        int offA[PPT], offB[PPT];
        {
            int4 y0 = __ldcs(yA4 + 2 * t);
            int4 y1 = __ldcs(yA4 + 2 * t + 1);
            int4 x0 = __ldcs(xA4 + 2 * t);
            int4 x1 = __ldcs(xA4 + 2 * t + 1);
            offA[0] = y0.x * WW + x0.x;  offA[1] = y0.y * WW + x0.y;
            offA[2] = y0.z * WW + x0.z;  offA[3] = y0.w * WW + x0.w;
            offA[4] = y1.x * WW + x1.x;  offA[5] = y1.y * WW + x1.y;
            offA[6] = y1.z * WW + x1.z;  offA[7] = y1.w * WW + x1.w;
        }
        {
            int4 y0 = __ldcs(yB4 + 2 * t);
            int4 y1 = __ldcs(yB4 + 2 * t + 1);
            int4 x0 = __ldcs(xB4 + 2 * t);
            int4 x1 = __ldcs(xB4 + 2 * t + 1);
            offB[0] = y0.x * WW + x0.x;  offB[1] = y0.y * WW + x0.y;
            offB[2] = y0.z * WW + x0.z;  offB[3] = y0.w * WW + x0.w;
            offB[4] = y1.x * WW + x1.x;  offB[5] = y1.y * WW + x1.y;
            offB[6] = y1.z * WW + x1.z;  offB[7] = y1.w * WW + x1.w;
        }

        // Issue all 16 gathers back-to-back (max MLP)
        float zA[PPT], zB[PPT];
        #pragma unroll
        for (int k = 0; k < PPT; k++) {
            zA[k] = __ldg(&img[offA[k]]);
            zB[k] = __ldg(&img[offB[k]]);
        }

        // Ordinals loaded last — consumed only in the compute phase
        int4 ov0 = __ldcs(ov4 + 2 * t);
        int4 ov1 = __ldcs(ov4 + 2 * t + 1);
        int ovv[PPT] = {ov0.x, ov0.y, ov0.z, ov0.w, ov1.x, ov1.y, ov1.z, ov1.w};

        #pragma unroll
        for (int k = 0; k < PPT; k++) {
            float diff = zA[k] - zB[k];
            float gt   = (float)(ovv[k] - 1);        // -1, 0, +1
            float mask = fabsf(gt);                  // 0 or 1
            float x    = -gt * diff;
            float sp   = fmaxf(x, 0.0f) + log1pf(expf(-fabsf(x)));
            l += mask * sp + (1.0f - mask) * diff * diff;
        }
    }

    // Warp reduction
    #pragma unroll
    for (int off = 16; off > 0; off >>= 1)
        l += __shfl_down_sync(0xffffffffu, l, off);

    __shared__ float warpsums[TPB / 32];
    const int lane = threadIdx.x & 31;
    const int wid  = threadIdx.x >> 5;
    if (lane == 0) warpsums[wid] = l;
    __syncthreads();

    __shared__ bool isLast;
    if (wid == 0) {
        float s = (lane < (TPB / 32)) ? warpsums[lane] : 0.0f;
        #pragma unroll
        for (int off = 4; off > 0; off >>= 1)
            s += __shfl_down_sync(0xffffffffu, s, off);
        if (lane == 0) {
            atomicAdd(&g_acc, (double)s);
            __threadfence();
            unsigned int old = atomicAdd(&g_count, 1u);
            isLast = (old == (unsigned int)(gridDim.x - 1));
        }
    }
    __syncthreads();

    // Last block finalizes and resets state for the next graph replay
    if (isLast && threadIdx.x == 0) {
        __threadfence();
        double acc = *((volatile double*)&g_acc);
        *out = (float)(acc / (double)TOTAL);
        *((volatile double*)&g_acc) = 0.0;
        __threadfence();
        *((volatile unsigned int*)&g_count) = 0u;
    }
}

extern "C" void kernel_launch(void* const* d_in, const int* in_sizes, int n_in,
                              void* d_out, int out_size)
{
    const float* depth = (const float*)d_in[0];
    const int*   xA    = (const int*)d_in[1];
    const int*   yA    = (const int*)d_in[2];
    const int*   xB    = (const int*)d_in[3];
    const int*   yB    = (const int*)d_in[4];
    const int*   ordv  = (const int*)d_in[5];
    float*       out   = (float*)d_out;

    loss_kernel<<<NBLOCKS, TPB>>>(depth, xA, yA, xB, yB, ordv, out);
}

// round 6
// speedup vs baseline: 1.0321x; 1.0321x over previous
#include <cuda_runtime.h>

// Problem constants (fixed by the reference):
//   input : (32, 1, 1024, 1024) float32
//   x_A, y_A, x_B, y_B, ordinal : (32, 100000) int32
//   output: scalar float32 = mean loss over 3.2M points
#define BB    32
#define HH    1024
#define WW    1024
#define NPTS  100000
#define TOTAL (BB * NPTS)        // 3,200,000
#define PPT   8                  // points per thread (NPTS % 8 == 0)
#define NTHREADS (TOTAL / PPT)   // 400,000
#define TPB   256
#define NBLOCKS ((NTHREADS + TPB - 1) / TPB)  // 1563 (last block partial)

__device__ double       g_acc   = 0.0;
__device__ unsigned int g_count = 0;

__global__ __launch_bounds__(TPB) void loss_kernel(
    const float* __restrict__ depth,
    const int*   __restrict__ xA,
    const int*   __restrict__ yA,
    const int*   __restrict__ xB,
    const int*   __restrict__ yB,
    const int*   __restrict__ ordv,
    float*       __restrict__ out)
{
    const int t = blockIdx.x * TPB + threadIdx.x;   // 0 .. 400127

    float l = 0.0f;
    if (t < NTHREADS) {
        // NPTS % 8 == 0 -> all 8 points of this thread share one batch
        const int b = t / (NPTS / PPT);             // t / 12500
        const float* __restrict__ img = depth + (size_t)b * (HH * WW);

        // Streaming vectorized index loads (touched once; evict-first in L2)
        const int4* xA4 = (const int4*)xA;
        const int4* yA4 = (const int4*)yA;
        const int4* xB4 = (const int4*)xB;
        const int4* yB4 = (const int4*)yB;
        const int4* ov4 = (const int4*)ordv;

        int4 ax0 = __ldcs(xA4 + 2 * t);
        int4 ax1 = __ldcs(xA4 + 2 * t + 1);
        int4 ay0 = __ldcs(yA4 + 2 * t);
        int4 ay1 = __ldcs(yA4 + 2 * t + 1);
        int4 bx0 = __ldcs(xB4 + 2 * t);
        int4 bx1 = __ldcs(xB4 + 2 * t + 1);
        int4 by0 = __ldcs(yB4 + 2 * t);
        int4 by1 = __ldcs(yB4 + 2 * t + 1);
        int4 ov0 = __ldcs(ov4 + 2 * t);
        int4 ov1 = __ldcs(ov4 + 2 * t + 1);

        int axv[PPT] = {ax0.x, ax0.y, ax0.z, ax0.w, ax1.x, ax1.y, ax1.z, ax1.w};
        int ayv[PPT] = {ay0.x, ay0.y, ay0.z, ay0.w, ay1.x, ay1.y, ay1.z, ay1.w};
        int bxv[PPT] = {bx0.x, bx0.y, bx0.z, bx0.w, bx1.x, bx1.y, bx1.z, bx1.w};
        int byv[PPT] = {by0.x, by0.y, by0.z, by0.w, by1.x, by1.y, by1.z, by1.w};
        int ovv[PPT] = {ov0.x, ov0.y, ov0.z, ov0.w, ov1.x, ov1.y, ov1.z, ov1.w};

        // Random 4B gathers: L2-only (.cg) — no L1 line allocation, exact
        // 32B-sector fetch (the nc/texture path may promote to 64B granules).
        float zA[PPT], zB[PPT];
        #pragma unroll
        for (int k = 0; k < PPT; k++) {
            zA[k] = __ldcg(&img[ayv[k] * WW + axv[k]]);
            zB[k] = __ldcg(&img[byv[k] * WW + bxv[k]]);
        }

        #pragma unroll
        for (int k = 0; k < PPT; k++) {
            float diff = zA[k] - zB[k];
            float gt   = (float)(ovv[k] - 1);        // -1, 0, +1
            float mask = fabsf(gt);                  // 0 or 1
            float x    = -gt * diff;
            float sp   = fmaxf(x, 0.0f) + log1pf(expf(-fabsf(x)));
            l += mask * sp + (1.0f - mask) * diff * diff;
        }
    }

    // Warp reduction
    #pragma unroll
    for (int off = 16; off > 0; off >>= 1)
        l += __shfl_down_sync(0xffffffffu, l, off);

    __shared__ float warpsums[TPB / 32];
    const int lane = threadIdx.x & 31;
    const int wid  = threadIdx.x >> 5;
    if (lane == 0) warpsums[wid] = l;
    __syncthreads();

    __shared__ bool isLast;
    if (wid == 0) {
        float s = (lane < (TPB / 32)) ? warpsums[lane] : 0.0f;
        #pragma unroll
        for (int off = 4; off > 0; off >>= 1)
            s += __shfl_down_sync(0xffffffffu, s, off);
        if (lane == 0) {
            atomicAdd(&g_acc, (double)s);
            __threadfence();
            unsigned int old = atomicAdd(&g_count, 1u);
            isLast = (old == (unsigned int)(gridDim.x - 1));
        }
    }
    __syncthreads();

    // Last block finalizes and resets state for the next graph replay
    if (isLast && threadIdx.x == 0) {
        __threadfence();
        double acc = *((volatile double*)&g_acc);
        *out = (float)(acc / (double)TOTAL);
        *((volatile double*)&g_acc) = 0.0;
        __threadfence();
        *((volatile unsigned int*)&g_count) = 0u;
    }
}

extern "C" void kernel_launch(void* const* d_in, const int* in_sizes, int n_in,
                              void* d_out, int out_size)
{
    const float* depth = (const float*)d_in[0];
    const int*   xA    = (const int*)d_in[1];
    const int*   yA    = (const int*)d_in[2];
    const int*   xB    = (const int*)d_in[3];
    const int*   yB    = (const int*)d_in[4];
    const int*   ordv  = (const int*)d_in[5];
    float*       out   = (float*)d_out;

    loss_kernel<<<NBLOCKS, TPB>>>(depth, xA, yA, xB, yB, ordv, out);
}

// round 7
// speedup vs baseline: 1.0379x; 1.0056x over previous
#include <cuda_runtime.h>

// Problem constants (fixed by the reference):
//   input : (32, 1, 1024, 1024) float32
//   x_A, y_A, x_B, y_B, ordinal : (32, 100000) int32
//   output: scalar float32 = mean loss over 3.2M points
//
// Converged design notes (R2-R6 evidence):
//  - memory-wall bound: ~207 MB DRAM vs ~192 MB compulsory floor at 64B
//    L2-miss granularity; DRAM busy ~60% (row-activation limited, random 64B)
//  - occupancy, MLP depth, L2 hints on indices: all proven non-binding
//  - __ldcg on gathers (skip L1 allocation): -1.2 us, kept
#define BB    32
#define HH    1024
#define WW    1024
#define NPTS  100000
#define TOTAL (BB * NPTS)        // 3,200,000
#define PPT   8                  // points per thread (NPTS % 8 == 0)
#define NTHREADS (TOTAL / PPT)   // 400,000
#define TPB   256
#define NBLOCKS ((NTHREADS + TPB - 1) / TPB)  // 1563 (last block partial)

__device__ double       g_acc   = 0.0;
__device__ unsigned int g_count = 0;

__global__ __launch_bounds__(TPB, 8) void loss_kernel(
    const float* __restrict__ depth,
    const int*   __restrict__ xA,
    const int*   __restrict__ yA,
    const int*   __restrict__ xB,
    const int*   __restrict__ yB,
    const int*   __restrict__ ordv,
    float*       __restrict__ out)
{
    const int t = blockIdx.x * TPB + threadIdx.x;   // 0 .. 400127

    float l = 0.0f;
    if (t < NTHREADS) {
        // NPTS % 8 == 0 -> all 8 points of this thread share one batch
        const int b = t / (NPTS / PPT);             // t / 12500
        const float* __restrict__ img = depth + (size_t)b * (HH * WW);

        const int4* xA4 = (const int4*)xA;
        const int4* yA4 = (const int4*)yA;
        const int4* xB4 = (const int4*)xB;
        const int4* yB4 = (const int4*)yB;
        const int4* ov4 = (const int4*)ordv;

        // Load coords (streaming), fold into flat offsets immediately
        // (register economy: 32 regs -> 8 blocks/SM)
        int offA[PPT], offB[PPT];
        {
            int4 y0 = __ldcs(yA4 + 2 * t);
            int4 y1 = __ldcs(yA4 + 2 * t + 1);
            int4 x0 = __ldcs(xA4 + 2 * t);
            int4 x1 = __ldcs(xA4 + 2 * t + 1);
            offA[0] = y0.x * WW + x0.x;  offA[1] = y0.y * WW + x0.y;
            offA[2] = y0.z * WW + x0.z;  offA[3] = y0.w * WW + x0.w;
            offA[4] = y1.x * WW + x1.x;  offA[5] = y1.y * WW + x1.y;
            offA[6] = y1.z * WW + x1.z;  offA[7] = y1.w * WW + x1.w;
        }
        {
            int4 y0 = __ldcs(yB4 + 2 * t);
            int4 y1 = __ldcs(yB4 + 2 * t + 1);
            int4 x0 = __ldcs(xB4 + 2 * t);
            int4 x1 = __ldcs(xB4 + 2 * t + 1);
            offB[0] = y0.x * WW + x0.x;  offB[1] = y0.y * WW + x0.y;
            offB[2] = y0.z * WW + x0.z;  offB[3] = y0.w * WW + x0.w;
            offB[4] = y1.x * WW + x1.x;  offB[5] = y1.y * WW + x1.y;
            offB[6] = y1.z * WW + x1.z;  offB[7] = y1.w * WW + x1.w;
        }

        // Random 4B gathers: L2-only (.cg), all 16 issued back-to-back
        float zA[PPT], zB[PPT];
        #pragma unroll
        for (int k = 0; k < PPT; k++) {
            zA[k] = __ldcg(&img[offA[k]]);
            zB[k] = __ldcg(&img[offB[k]]);
        }

        // Ordinals last — consumed only in the compute phase
        int4 ov0 = __ldcs(ov4 + 2 * t);
        int4 ov1 = __ldcs(ov4 + 2 * t + 1);
        int ovv[PPT] = {ov0.x, ov0.y, ov0.z, ov0.w, ov1.x, ov1.y, ov1.z, ov1.w};

        #pragma unroll
        for (int k = 0; k < PPT; k++) {
            float diff = zA[k] - zB[k];
            float gt   = (float)(ovv[k] - 1);        // -1, 0, +1
            float mask = fabsf(gt);                  // 0 or 1
            float x    = -gt * diff;
            float sp   = fmaxf(x, 0.0f) + log1pf(expf(-fabsf(x)));
            l += mask * sp + (1.0f - mask) * diff * diff;
        }
    }

    // Warp reduction
    #pragma unroll
    for (int off = 16; off > 0; off >>= 1)
        l += __shfl_down_sync(0xffffffffu, l, off);

    __shared__ float warpsums[TPB / 32];
    const int lane = threadIdx.x & 31;
    const int wid  = threadIdx.x >> 5;
    if (lane == 0) warpsums[wid] = l;
    __syncthreads();

    __shared__ bool isLast;
    if (wid == 0) {
        float s = (lane < (TPB / 32)) ? warpsums[lane] : 0.0f;
        #pragma unroll
        for (int off = 4; off > 0; off >>= 1)
            s += __shfl_down_sync(0xffffffffu, s, off);
        if (lane == 0) {
            atomicAdd(&g_acc, (double)s);
            __threadfence();
            unsigned int old = atomicAdd(&g_count, 1u);
            isLast = (old == (unsigned int)(gridDim.x - 1));
        }
    }
    __syncthreads();

    // Last block finalizes and resets state for the next graph replay
    if (isLast && threadIdx.x == 0) {
        __threadfence();
        double acc = *((volatile double*)&g_acc);
        *out = (float)(acc / (double)TOTAL);
        *((volatile double*)&g_acc) = 0.0;
        __threadfence();
        *((volatile unsigned int*)&g_count) = 0u;
    }
}

extern "C" void kernel_launch(void* const* d_in, const int* in_sizes, int n_in,
                              void* d_out, int out_size)
{
    const float* depth = (const float*)d_in[0];
    const int*   xA    = (const int*)d_in[1];
    const int*   yA    = (const int*)d_in[2];
    const int*   xB    = (const int*)d_in[3];
    const int*   yB    = (const int*)d_in[4];
    const int*   ordv  = (const int*)d_in[5];
    float*       out   = (float*)d_out;

    loss_kernel<<<NBLOCKS, TPB>>>(depth, xA, yA, xB, yB, ordv, out);
}